// round 1
// baseline (speedup 1.0000x reference)
#include <cuda_runtime.h>

// FWHT of 4096-wide rows with sign flip + 1/64 normalization.
// One CTA (256 threads) per row; 16 fp32 values per thread.
// Stage plan over the 12 index bits (strides 1..2048):
//   Round 1 layout: i = g*1024 + t*4 + c   (k = g*4+c held in registers)
//     - registers:  strides 1,2,1024,2048  (H16 over k)
//     - shuffles:   strides 4,8,16,32,64   (lane bits i[6:2])
//   One 16KB shared exchange (vectorized, conflict-free).
//   Round 2 layout: i[1:0]=j[1:0], i[9:8]=j[3:2], i[7]=lane[4],
//                   i[5:2]=lane[3:0], i[6]=warp[0], i[11:10]=warp[2:1]
//     - shuffle:    stride 128 (lane bit 4)
//     - registers:  strides 256,512 (j bits 2,3)
//   float4 coalesced global load/store; scale folded into load.

#define FWHT_D 4096

__global__ __launch_bounds__(256) void RHTRotation_82394652607202_kernel(
    const float* __restrict__ x,
    const float* __restrict__ signs,
    float* __restrict__ out)
{
    __shared__ float sm[FWHT_D];

    const int t    = threadIdx.x;     // 0..255
    const int lane = t & 31;
    const int wrp  = t >> 5;          // 0..7

    const long long rowoff = (long long)blockIdx.x * FWHT_D;
    const float* xr  = x   + rowoff;
    float*       outr = out + rowoff;

    float r[16];
    const float scale = 0.015625f;    // 4096^-0.5 (exact)

    // ---- load (fully coalesced float4), fold signs * scale ----
    #pragma unroll
    for (int g = 0; g < 4; ++g) {
        const int off = g * 1024 + t * 4;
        const float4 v = *reinterpret_cast<const float4*>(xr + off);
        const float4 s = *reinterpret_cast<const float4*>(signs + off);
        r[g * 4 + 0] = v.x * (s.x * scale);
        r[g * 4 + 1] = v.y * (s.y * scale);
        r[g * 4 + 2] = v.z * (s.z * scale);
        r[g * 4 + 3] = v.w * (s.w * scale);
    }

    // ---- register H16 over k: i-strides 1, 2, 1024, 2048 ----
    #pragma unroll
    for (int p = 1; p < 16; p <<= 1) {
        #pragma unroll
        for (int k = 0; k < 16; ++k) {
            if ((k & p) == 0) {
                const float a = r[k];
                const float b = r[k | p];
                r[k]     = a + b;
                r[k | p] = a - b;
            }
        }
    }

    // ---- shuffle stages: lane bits -> i-strides 4, 8, 16, 32, 64 ----
    #pragma unroll
    for (int s = 1; s <= 16; s <<= 1) {
        const float sgn = (lane & s) ? -1.0f : 1.0f;
        #pragma unroll
        for (int k = 0; k < 16; ++k) {
            const float o = __shfl_xor_sync(0xffffffffu, r[k], s);
            r[k] = fmaf(sgn, r[k], o);   // lower: r+o ; upper: o-r
        }
    }

    // ---- one shared exchange (STS.128 / LDS.128, minimal phases) ----
    #pragma unroll
    for (int g = 0; g < 4; ++g) {
        *reinterpret_cast<float4*>(sm + g * 1024 + t * 4) =
            make_float4(r[g * 4 + 0], r[g * 4 + 1], r[g * 4 + 2], r[g * 4 + 3]);
    }
    __syncthreads();

    // Round-2 base: bits [11:10]=wrp>>1, [7]=lane>>4, [6]=wrp&1, [5:2]=lane&15
    const int base = ((wrp >> 1) << 10) | (((lane >> 4) & 1) << 7) |
                     ((wrp & 1) << 6)   | ((lane & 15) << 2);

    #pragma unroll
    for (int jj = 0; jj < 4; ++jj) {
        const float4 v = *reinterpret_cast<const float4*>(sm + base + (jj << 8));
        r[jj * 4 + 0] = v.x;
        r[jj * 4 + 1] = v.y;
        r[jj * 4 + 2] = v.z;
        r[jj * 4 + 3] = v.w;
    }

    // ---- stride 128 via shuffle on lane bit 4 ----
    {
        const float sgn = (lane & 16) ? -1.0f : 1.0f;
        #pragma unroll
        for (int k = 0; k < 16; ++k) {
            const float o = __shfl_xor_sync(0xffffffffu, r[k], 16);
            r[k] = fmaf(sgn, r[k], o);
        }
    }

    // ---- strides 256, 512 via register bits j[2], j[3] ----
    #pragma unroll
    for (int p = 4; p <= 8; p <<= 1) {
        #pragma unroll
        for (int k = 0; k < 16; ++k) {
            if ((k & p) == 0) {
                const float a = r[k];
                const float b = r[k | p];
                r[k]     = a + b;
                r[k | p] = a - b;
            }
        }
    }

    // ---- store (fully coalesced float4) ----
    #pragma unroll
    for (int jj = 0; jj < 4; ++jj) {
        *reinterpret_cast<float4*>(outr + base + (jj << 8)) =
            make_float4(r[jj * 4 + 0], r[jj * 4 + 1], r[jj * 4 + 2], r[jj * 4 + 3]);
    }
}

extern "C" void kernel_launch(void* const* d_in, const int* in_sizes, int n_in,
                              void* d_out, int out_size)
{
    const float* a = (const float*)d_in[0];
    const float* b = (const float*)d_in[1];
    // x is [N, 4096], signs is [4096] — identify by element count.
    const float* x;
    const float* signs;
    if (in_sizes[0] == FWHT_D && in_sizes[1] > FWHT_D) { signs = a; x = b; }
    else                                               { x = a; signs = b; }

    const int rows = out_size / FWHT_D;
    RHTRotation_82394652607202_kernel<<<rows, 256>>>(x, signs, (float*)d_out);
}

// round 2
// speedup vs baseline: 1.0788x; 1.0788x over previous
#include <cuda_runtime.h>

// FWHT of 4096-wide rows, sign flip + 2^-6 normalization.
// Zero shuffles. One CTA (256 thr) per row, 16 fp32/thread, three register-H16
// rounds separated by two swizzled shared-memory exchanges.
//
//   Round 1: i = t*16 + k            -> strides 1,2,4,8     (i bits [3:0])
//   Round 2: i = t[7:4]<<8|k<<4|t[3:0] -> strides 16..128   (i bits [7:4])
//   Round 3: i = k<<8 | t            -> strides 256..2048   (i bits [11:8])
//
// Shared swizzle s(i) = i ^ ((i>>5 & 3)<<2) ^ ((i>>8 & 1)<<4 makes every
// access pattern bank-conflict-free (STS.128 per quarter-warp, scalar
// LDS/STS per full warp). Signs are pre-packed to bits by a tiny kernel;
// sign and scale are applied with one FMUL per element using +-2^-6
// constructed by bit ops (0x3C800000 | signbit).

#define FWHT_D 4096

__device__ unsigned g_signbits[FWHT_D / 32];

__global__ void pack_signs_kernel(const float* __restrict__ signs)
{
    const int j = threadIdx.x;           // 0..127
    unsigned w = 0;
    #pragma unroll
    for (int k = 0; k < 32; ++k)
        w |= (__float_as_uint(signs[j * 32 + k]) >> 31) << k;
    g_signbits[j] = w;
}

__device__ __forceinline__ int swz(int i)
{
    return i ^ (((i >> 5) & 3) << 2) ^ (((i >> 8) & 1) << 4);
}

__device__ __forceinline__ void h16(float (&r)[16])
{
    #pragma unroll
    for (int p = 1; p < 16; p <<= 1) {
        #pragma unroll
        for (int k = 0; k < 16; ++k) {
            if ((k & p) == 0) {
                const float a = r[k];
                const float b = r[k | p];
                r[k]     = a + b;
                r[k | p] = a - b;
            }
        }
    }
}

__global__ __launch_bounds__(256) void RHTRotation_82394652607202_kernel(
    const float* __restrict__ x,
    float* __restrict__ out)
{
    __shared__ float sm[FWHT_D];

    const int t = threadIdx.x;                    // 0..255
    const long long rowoff = (long long)blockIdx.x * FWHT_D;
    const float* xr   = x   + rowoff;
    float*       outr = out + rowoff;

    // 16 sign bits for this thread's phase-1 elements (i = t*16 + k).
    const unsigned u = g_signbits[t >> 1] >> ((t & 1) * 16);

    float r[16];

    // ---- load (float4) + fused sign*scale: m = +-2^-6 ----
    #pragma unroll
    for (int g = 0; g < 4; ++g) {
        const float4 v = *reinterpret_cast<const float4*>(xr + t * 16 + g * 4);
        #pragma unroll
        for (int c = 0; c < 4; ++c) {
            const int k = g * 4 + c;
            const unsigned sbit = (u << (31 - k)) & 0x80000000u;
            const float m = __uint_as_float(0x3C800000u | sbit);   // +-0.015625
            const float val = (c == 0) ? v.x : (c == 1) ? v.y : (c == 2) ? v.z : v.w;
            r[k] = val * m;
        }
    }

    // ---- round 1: strides 1,2,4,8 ----
    h16(r);

    // ---- exchange 1: store at i = t*16 + k (swizzled float4) ----
    #pragma unroll
    for (int g = 0; g < 4; ++g) {
        const int i = t * 16 + g * 4;             // quad-aligned; swz keeps bits [1:0]
        *reinterpret_cast<float4*>(sm + swz(i)) =
            make_float4(r[g * 4 + 0], r[g * 4 + 1], r[g * 4 + 2], r[g * 4 + 3]);
    }
    __syncthreads();

    // ---- round 2: i = (t>>4)<<8 | k<<4 | (t&15) ----
    const int hi = t >> 4;
    const int lo = t & 15;
    const int base2 = (hi << 8) | lo;
    #pragma unroll
    for (int k = 0; k < 16; ++k)
        r[k] = sm[swz(base2 | (k << 4))];

    h16(r);                                       // strides 16,32,64,128

    // write back to the SAME addresses this thread just read: no barrier needed
    #pragma unroll
    for (int k = 0; k < 16; ++k)
        sm[swz(base2 | (k << 4))] = r[k];
    __syncthreads();

    // ---- round 3: i = k<<8 | t ----
    #pragma unroll
    for (int k = 0; k < 16; ++k)
        r[k] = sm[swz((k << 8) | t)];

    h16(r);                                       // strides 256,512,1024,2048

    // ---- store: out[k<<8 | t], perfectly coalesced 128B per instruction ----
    #pragma unroll
    for (int k = 0; k < 16; ++k)
        outr[(k << 8) + t] = r[k];
}

extern "C" void kernel_launch(void* const* d_in, const int* in_sizes, int n_in,
                              void* d_out, int out_size)
{
    const float* a = (const float*)d_in[0];
    const float* b = (const float*)d_in[1];
    const float* x;
    const float* signs;
    if (in_sizes[0] == FWHT_D && in_sizes[1] > FWHT_D) { signs = a; x = b; }
    else                                               { x = a; signs = b; }

    pack_signs_kernel<<<1, 128>>>(signs);

    const int rows = out_size / FWHT_D;
    RHTRotation_82394652607202_kernel<<<rows, 256>>>(x, (float*)d_out);
}

// round 3
// speedup vs baseline: 1.1040x; 1.0234x over previous
#include <cuda_runtime.h>

// FWHT of 4096-wide rows, sign flip + 2^-6 normalization.
// One CTA (256 thr) per row, 16 fp32/thread, three register-H16 rounds
// separated by two shared-memory exchanges.
//
//   Round 1: i = t*16 + k              -> strides 1,2,4,8     (i bits [3:0])
//   Round 2: i = t[7:4]<<8|k<<4|t[3:0] -> strides 16..128     (i bits [7:4])
//   Round 3: i = k<<8 | t              -> strides 256..2048   (i bits [11:8])
//
// Shared layout is PAD-17: addr(i) = (i>>4)*17 + (i&15). All three access
// patterns are bank-conflict-free (verified mod-32 per warp) AND all offsets
// within the unrolled k-loops are compile-time immediates -> zero ALU per
// shared access (pure LDS/STS [R+imm]).
// Signs are pre-packed to a 128-word bitmask by a ballot kernel; sign+scale
// fuse into one FMUL per element with +-2^-6 built by bit ops.

#define FWHT_D 4096
#define PADROW 17   // floats per 16-element row in shared

__device__ unsigned g_signbits[FWHT_D / 32];

__global__ void pack_signs_kernel(const float* __restrict__ signs)
{
    const int i = blockIdx.x * blockDim.x + threadIdx.x;   // 0..4095
    const unsigned sb = __float_as_uint(signs[i]) >> 31;
    const unsigned w = __ballot_sync(0xffffffffu, sb);
    if ((i & 31) == 0)
        g_signbits[i >> 5] = w;
}

__device__ __forceinline__ void h16(float (&r)[16])
{
    #pragma unroll
    for (int p = 1; p < 16; p <<= 1) {
        #pragma unroll
        for (int k = 0; k < 16; ++k) {
            if ((k & p) == 0) {
                const float a = r[k];
                const float b = r[k | p];
                r[k]     = a + b;
                r[k | p] = a - b;
            }
        }
    }
}

__global__ __launch_bounds__(256) void RHTRotation_82394652607202_kernel(
    const float* __restrict__ x,
    float* __restrict__ out)
{
    __shared__ float sm[256 * PADROW];

    const int t = threadIdx.x;                    // 0..255
    const long long rowoff = (long long)blockIdx.x * FWHT_D;
    const float* xr   = x   + rowoff;
    float*       outr = out + rowoff;

    // 16 sign bits for this thread's phase-1 elements (i = t*16 + k).
    const unsigned u = g_signbits[t >> 1] >> ((t & 1) * 16);

    float r[16];

    // ---- load (float4) + fused sign*scale: m = +-2^-6 ----
    #pragma unroll
    for (int g = 0; g < 4; ++g) {
        const float4 v = *reinterpret_cast<const float4*>(xr + t * 16 + g * 4);
        #pragma unroll
        for (int c = 0; c < 4; ++c) {
            const int k = g * 4 + c;
            const unsigned sbit = (u << (31 - k)) & 0x80000000u;
            const float m = __uint_as_float(0x3C800000u | sbit);   // +-0.015625
            const float val = (c == 0) ? v.x : (c == 1) ? v.y : (c == 2) ? v.z : v.w;
            r[k] = val * m;
        }
    }

    // ---- round 1: strides 1,2,4,8 ----
    h16(r);

    // ---- exchange 1: store at i = t*16+k  ->  addr = t*17 + k (imm) ----
    {
        float* s1 = sm + t * PADROW;
        #pragma unroll
        for (int k = 0; k < 16; ++k)
            s1[k] = r[k];
    }
    __syncthreads();

    // ---- round 2: i = (t>>4)<<8 | k<<4 | (t&15) ----
    //      addr = (t>>4)*272 + (t&15) + k*17 (imm)
    float* s2 = sm + (t >> 4) * (16 * PADROW) + (t & 15);
    #pragma unroll
    for (int k = 0; k < 16; ++k)
        r[k] = s2[k * PADROW];

    h16(r);                                       // strides 16,32,64,128

    // write back to the SAME addresses this thread just read: no barrier needed
    #pragma unroll
    for (int k = 0; k < 16; ++k)
        s2[k * PADROW] = r[k];
    __syncthreads();

    // ---- round 3: i = k<<8 | t ----
    //      addr = (t>>4)*17 + (t&15) + k*272 (imm)
    const float* s3 = sm + (t >> 4) * PADROW + (t & 15);
    #pragma unroll
    for (int k = 0; k < 16; ++k)
        r[k] = s3[k * (16 * PADROW)];

    h16(r);                                       // strides 256,512,1024,2048

    // ---- store: out[k<<8 | t], coalesced 128B per instruction, imm offsets ----
    #pragma unroll
    for (int k = 0; k < 16; ++k)
        outr[(k << 8) + t] = r[k];
}

extern "C" void kernel_launch(void* const* d_in, const int* in_sizes, int n_in,
                              void* d_out, int out_size)
{
    const float* a = (const float*)d_in[0];
    const float* b = (const float*)d_in[1];
    const float* x;
    const float* signs;
    if (in_sizes[0] == FWHT_D && in_sizes[1] > FWHT_D) { signs = a; x = b; }
    else                                               { x = a; signs = b; }

    pack_signs_kernel<<<FWHT_D / 512, 512>>>(signs);

    const int rows = out_size / FWHT_D;
    RHTRotation_82394652607202_kernel<<<rows, 256>>>(x, (float*)d_out);
}